// round 2
// baseline (speedup 1.0000x reference)
#include <cuda_runtime.h>
#include <cstdint>

// ---------------- problem dims ----------------
#define B_   2
#define T_   2048
#define HID  2048
#define NH   6
#define DK   256
#define DV   512
#define KD   1536      // NH*DK
#define VD   3072      // NH*DV
#define BT   4096      // B_*T_
#define CK   4

typedef unsigned long long ull;

// ---------------- scratch (device globals; no allocs allowed) ----------------
__device__ float d_QP[BT * KD];
__device__ float d_KP[BT * KD];
__device__ float d_VP[(size_t)BT * VD];
__device__ float d_GP[(size_t)BT * VD];
__device__ float d_Qc[BT * KD];
__device__ float d_Kc[BT * KD];
__device__ float d_Vc[(size_t)BT * VD];
__device__ float d_EG[BT * NH];
__device__ float d_Beta[BT * NH];
__device__ float d_O[(size_t)BT * VD];
__device__ float d_ONG[(size_t)BT * VD];

// ---------------- packed f32x2 helpers (Blackwell FFMA2 path) ----------------
__device__ __forceinline__ ull fma2(ull a, ull b, ull c) {
    ull d;
    asm("fma.rn.f32x2 %0, %1, %2, %3;" : "=l"(d) : "l"(a), "l"(b), "l"(c));
    return d;
}
__device__ __forceinline__ ull mul2(ull a, ull b) {
    ull d;
    asm("mul.rn.f32x2 %0, %1, %2;" : "=l"(d) : "l"(a), "l"(b));
    return d;
}
__device__ __forceinline__ ull pack2(float lo, float hi) {
    ull d;
    asm("mov.b64 %0, {%1, %2};" : "=l"(d) : "f"(lo), "f"(hi));
    return d;
}
__device__ __forceinline__ void unpack2(ull v, float& lo, float& hi) {
    asm("mov.b64 {%0, %1}, %2;" : "=f"(lo), "=f"(hi) : "l"(v));
}

__device__ __forceinline__ float sigm(float x) { return 1.0f / (1.0f + __expf(-x)); }
__device__ __forceinline__ float wredux(float v) {
#pragma unroll
    for (int m = 16; m > 0; m >>= 1) v += __shfl_xor_sync(0xffffffffu, v, m);
    return v;
}

// ---------------- fp32 SGEMM, 128x128 tile, BK=8, packed f32x2 inner ----------------
// C[M,N] = A[M,K] @ B[K,N], all row-major, M%128==0, N%128==0, K%8==0
__global__ __launch_bounds__(256) void gemm128(const float* __restrict__ A,
                                               const float* __restrict__ Bm,
                                               float* __restrict__ C,
                                               int M, int N, int K) {
    __shared__ float As[2][8][128];
    __shared__ float Bs[2][8][128];
    const int tid = threadIdx.x;
    const int tx = tid & 15, ty = tid >> 4;
    const int arow = tid >> 1, acol = (tid & 1) * 4;
    const int brow = tid >> 5, bcol = (tid & 31) * 4;
    const float* Ab = A + (size_t)blockIdx.y * 128 * K;
    const float* Bb = Bm + blockIdx.x * 128;

    ull acc[8][4];
#pragma unroll
    for (int i = 0; i < 8; i++)
#pragma unroll
        for (int p = 0; p < 4; p++) acc[i][p] = 0ull;

    float4 pa = *(const float4*)(Ab + (size_t)arow * K + acol);
    float4 pb = *(const float4*)(Bb + (size_t)brow * N + bcol);
    As[0][acol + 0][arow] = pa.x; As[0][acol + 1][arow] = pa.y;
    As[0][acol + 2][arow] = pa.z; As[0][acol + 3][arow] = pa.w;
    *(float4*)&Bs[0][brow][bcol] = pb;
    __syncthreads();

    const int NT = K >> 3;
    int buf = 0;
    for (int kt = 1; kt <= NT; kt++) {
        if (kt < NT) {
            pa = *(const float4*)(Ab + (size_t)arow * K + kt * 8 + acol);
            pb = *(const float4*)(Bb + (size_t)(kt * 8 + brow) * N + bcol);
        }
#pragma unroll
        for (int k = 0; k < 8; k++) {
            float4 av0 = *(const float4*)&As[buf][k][ty * 8];
            float4 av1 = *(const float4*)&As[buf][k][ty * 8 + 4];
            ulonglong2 bl0 = *(const ulonglong2*)&Bs[buf][k][tx * 8];
            ulonglong2 bl1 = *(const ulonglong2*)&Bs[buf][k][tx * 8 + 4];
            ull b2[4] = {bl0.x, bl0.y, bl1.x, bl1.y};
            float a8[8] = {av0.x, av0.y, av0.z, av0.w, av1.x, av1.y, av1.z, av1.w};
#pragma unroll
            for (int i = 0; i < 8; i++) {
                ull a2 = pack2(a8[i], a8[i]);
#pragma unroll
                for (int p = 0; p < 4; p++) acc[i][p] = fma2(a2, b2[p], acc[i][p]);
            }
        }
        if (kt < NT) {
            int nb = buf ^ 1;
            As[nb][acol + 0][arow] = pa.x; As[nb][acol + 1][arow] = pa.y;
            As[nb][acol + 2][arow] = pa.z; As[nb][acol + 3][arow] = pa.w;
            *(float4*)&Bs[nb][brow][bcol] = pb;
        }
        __syncthreads();
        buf ^= 1;
    }

    float* Cp = C + (size_t)(blockIdx.y * 128 + ty * 8) * N + blockIdx.x * 128 + tx * 8;
#pragma unroll
    for (int i = 0; i < 8; i++) {
        float4 c0, c1;
        unpack2(acc[i][0], c0.x, c0.y); unpack2(acc[i][1], c0.z, c0.w);
        unpack2(acc[i][2], c1.x, c1.y); unpack2(acc[i][3], c1.z, c1.w);
        *(float4*)(Cp + (size_t)i * N) = c0;
        *(float4*)(Cp + (size_t)i * N + 4) = c1;
    }
}

// ---------------- gate projections: g -> exp(g), beta ----------------
// one block per token; 12 small dot products of the hidden row
__global__ __launch_bounds__(256) void gate_kernel(const float* __restrict__ H,
                                                   const float* __restrict__ Wa,
                                                   const float* __restrict__ Wb,
                                                   const float* __restrict__ A_log,
                                                   const float* __restrict__ dt_bias) {
    __shared__ float hrow[HID];
    const int bt = blockIdx.x;
    const int tid = threadIdx.x;
    for (int i = tid; i < HID; i += 256) hrow[i] = H[(size_t)bt * HID + i];
    __syncthreads();
    const int w = tid >> 5, lane = tid & 31;
    for (int d = w; d < 12; d += 8) {
        const int head = d % 6;
        const float* Wc = (d < 6) ? Wa : Wb;
        float s = 0.0f;
        for (int i = lane; i < HID; i += 32) s += hrow[i] * Wc[i * NH + head];
#pragma unroll
        for (int m = 16; m > 0; m >>= 1) s += __shfl_xor_sync(0xffffffffu, s, m);
        if (lane == 0) {
            if (d < 6) {
                float x = s + dt_bias[head];
                float sp = (x > 20.0f) ? x : log1pf(expf(x));
                float g = -expf(A_log[head]) * sp;
                d_EG[bt * NH + head] = expf(g);
            } else {
                d_Beta[bt * NH + head] = sigm(s);
            }
        }
    }
}

// ---------------- causal depthwise conv + silu + per-head l2norm (q/k) ----------------
__global__ __launch_bounds__(256) void convqk_kernel(const float* __restrict__ P,
                                                     const float* __restrict__ W,
                                                     float* __restrict__ out,
                                                     float scale) {
    const int bt = blockIdx.x;
    const int h = blockIdx.y;
    const int c = threadIdx.x;
    const int ch = h * DK + c;
    const int t = bt & (T_ - 1);
    float acc = 0.0f;
#pragma unroll
    for (int j = 0; j < CK; j++) {
        int tt = t - (CK - 1) + j;
        if (tt >= 0) acc += P[(size_t)(bt - (CK - 1) + j) * KD + ch] * W[ch * CK + j];
    }
    float y = acc * sigm(acc);  // silu

    // block reduce sum of squares over 256 channels
    __shared__ float red[8];
    float ss = y * y;
#pragma unroll
    for (int m = 16; m > 0; m >>= 1) ss += __shfl_xor_sync(0xffffffffu, ss, m);
    if ((c & 31) == 0) red[c >> 5] = ss;
    __syncthreads();
    float tot = 0.0f;
#pragma unroll
    for (int i = 0; i < 8; i++) tot += red[i];
    float r = rsqrtf(tot + 1e-6f);
    out[(size_t)bt * KD + ch] = y * r * scale;
}

// ---------------- causal depthwise conv + silu (v) ----------------
__global__ __launch_bounds__(256) void convv_kernel(const float* __restrict__ P,
                                                    const float* __restrict__ W) {
    const int bt = blockIdx.x;
    const int ch = blockIdx.y * 256 + threadIdx.x;
    const int t = bt & (T_ - 1);
    float acc = 0.0f;
#pragma unroll
    for (int j = 0; j < CK; j++) {
        int tt = t - (CK - 1) + j;
        if (tt >= 0) acc += P[(size_t)(bt - (CK - 1) + j) * VD + ch] * W[ch * CK + j];
    }
    d_Vc[(size_t)bt * VD + ch] = acc * sigm(acc);
}

// ---------------- gated delta-rule recurrence ----------------
// grid = 96 CTAs: (b,h) x 8 chunks of DV=64. State S[256,64] fp32 in registers
// (packed f32x2 over the DV dimension). 8 warps per CTA; warp w owns cols
// [chunk*64 + w*8, +8); lane owns rows [8*lane, 8*lane+8).
__global__ __launch_bounds__(256, 1) void recur_kernel() {
    const int bid = blockIdx.x;
    const int chunk = bid & 7;
    const int bh = bid >> 3;
    const int b = bh / NH, h = bh % NH;
    const int warp = threadIdx.x >> 5, lane = threadIdx.x & 31;
    const int colbase = chunk * 64 + warp * 8;

    ull S[8][4];
#pragma unroll
    for (int r = 0; r < 8; r++)
#pragma unroll
        for (int p = 0; p < 4; p++) S[r][p] = 0ull;

    const float* Kbase = d_Kc + h * DK + lane * 8;
    const float* Qbase = d_Qc + h * DK + lane * 8;
    const float* Vbase = d_Vc + h * DV + colbase;
    float* Obase = d_O + h * DV + colbase;
    const int bt0 = b * T_;

    for (int t = 0; t < T_; t++) {
        const int bt = bt0 + t;
        const float4 k0 = *(const float4*)(Kbase + (size_t)bt * KD);
        const float4 k1 = *(const float4*)(Kbase + (size_t)bt * KD + 4);
        const float4 q0 = *(const float4*)(Qbase + (size_t)bt * KD);
        const float4 q1 = *(const float4*)(Qbase + (size_t)bt * KD + 4);
        const float4 v0 = *(const float4*)(Vbase + (size_t)bt * VD);
        const float4 v1 = *(const float4*)(Vbase + (size_t)bt * VD + 4);
        const float eg = d_EG[bt * NH + h];
        const float bet = d_Beta[bt * NH + h];

        float kk[8] = {k0.x, k0.y, k0.z, k0.w, k1.x, k1.y, k1.z, k1.w};
        float qq[8] = {q0.x, q0.y, q0.z, q0.w, q1.x, q1.y, q1.z, q1.w};
        float vv[8] = {v0.x, v0.y, v0.z, v0.w, v1.x, v1.y, v1.z, v1.w};

        // phase 1: kv_pre = k . S  (pre-decay; decay folded in scalar later)
        ull kv2[4] = {0ull, 0ull, 0ull, 0ull};
#pragma unroll
        for (int r = 0; r < 8; r++) {
            ull k2 = pack2(kk[r], kk[r]);
#pragma unroll
            for (int p = 0; p < 4; p++) kv2[p] = fma2(k2, S[r][p], kv2[p]);
        }
        float kv[8];
        unpack2(kv2[0], kv[0], kv[1]); unpack2(kv2[1], kv[2], kv[3]);
        unpack2(kv2[2], kv[4], kv[5]); unpack2(kv2[3], kv[6], kv[7]);
#pragma unroll
        for (int j = 0; j < 8; j++) kv[j] = wredux(kv[j]);

        // u = (v - eg * kv_pre) * beta
        ull u2[4];
#pragma unroll
        for (int p = 0; p < 4; p++) {
            float u0 = (vv[2 * p]     - eg * kv[2 * p])     * bet;
            float u1 = (vv[2 * p + 1] - eg * kv[2 * p + 1]) * bet;
            u2[p] = pack2(u0, u1);
        }
        const ull eg2 = pack2(eg, eg);

        // phase 2: S = eg*S + k (x) u ; o_partial = q . S
        ull o2[4] = {0ull, 0ull, 0ull, 0ull};
#pragma unroll
        for (int r = 0; r < 8; r++) {
            ull k2 = pack2(kk[r], kk[r]);
            ull q2 = pack2(qq[r], qq[r]);
#pragma unroll
            for (int p = 0; p < 4; p++) {
                S[r][p] = fma2(eg2, S[r][p], mul2(k2, u2[p]));
                o2[p]   = fma2(q2, S[r][p], o2[p]);
            }
        }
        float oo[8];
        unpack2(o2[0], oo[0], oo[1]); unpack2(o2[1], oo[2], oo[3]);
        unpack2(o2[2], oo[4], oo[5]); unpack2(o2[3], oo[6], oo[7]);
#pragma unroll
        for (int j = 0; j < 8; j++) oo[j] = wredux(oo[j]);
        if (lane < 8) Obase[(size_t)bt * VD + lane] = oo[lane];
    }
}

// ---------------- gated RMSNorm ----------------
__global__ __launch_bounds__(256) void normgate_kernel(const float* __restrict__ w) {
    const int bt = blockIdx.x;
    const int h = blockIdx.y;
    const int tid = threadIdx.x;
    const size_t base = (size_t)bt * VD + h * DV;
    float o0 = d_O[base + tid];
    float o1 = d_O[base + tid + 256];
    float ss = o0 * o0 + o1 * o1;
    __shared__ float red[8];
#pragma unroll
    for (int m = 16; m > 0; m >>= 1) ss += __shfl_xor_sync(0xffffffffu, ss, m);
    if ((tid & 31) == 0) red[tid >> 5] = ss;
    __syncthreads();
    float tot = 0.0f;
#pragma unroll
    for (int i = 0; i < 8; i++) tot += red[i];
    float rms = rsqrtf(tot * (1.0f / (float)DV) + 1e-5f);
    float g0 = d_GP[base + tid];
    float g1 = d_GP[base + tid + 256];
    d_ONG[base + tid]       = o0 * rms * w[tid]       * g0 * sigm(g0);
    d_ONG[base + tid + 256] = o1 * rms * w[tid + 256] * g1 * sigm(g1);
}

// ---------------- host launcher ----------------
extern "C" void kernel_launch(void* const* d_in, const int* in_sizes, int n_in,
                              void* d_out, int out_size) {
    const float* H       = (const float*)d_in[0];
    const float* Wq      = (const float*)d_in[1];
    const float* Wk      = (const float*)d_in[2];
    const float* Wv      = (const float*)d_in[3];
    const float* Wa      = (const float*)d_in[4];
    const float* Wb      = (const float*)d_in[5];
    const float* Wg      = (const float*)d_in[6];
    const float* Wo      = (const float*)d_in[7];
    const float* conv_q  = (const float*)d_in[8];
    const float* conv_k  = (const float*)d_in[9];
    const float* conv_v  = (const float*)d_in[10];
    const float* A_log   = (const float*)d_in[11];
    const float* dt_bias = (const float*)d_in[12];
    const float* onw     = (const float*)d_in[13];

    float *qp, *kp, *vp, *gp, *qc, *kc, *ong;
    cudaGetSymbolAddress((void**)&qp, d_QP);
    cudaGetSymbolAddress((void**)&kp, d_KP);
    cudaGetSymbolAddress((void**)&vp, d_VP);
    cudaGetSymbolAddress((void**)&gp, d_GP);
    cudaGetSymbolAddress((void**)&qc, d_Qc);
    cudaGetSymbolAddress((void**)&kc, d_Kc);
    cudaGetSymbolAddress((void**)&ong, d_ONG);

    // projections
    gemm128<<<dim3(KD / 128, BT / 128), 256>>>(H, Wq, qp, BT, KD, HID);
    gemm128<<<dim3(KD / 128, BT / 128), 256>>>(H, Wk, kp, BT, KD, HID);
    gemm128<<<dim3(VD / 128, BT / 128), 256>>>(H, Wv, vp, BT, VD, HID);
    gemm128<<<dim3(VD / 128, BT / 128), 256>>>(H, Wg, gp, BT, VD, HID);
    gate_kernel<<<BT, 256>>>(H, Wa, Wb, A_log, dt_bias);

    // conv + act (+ l2norm for q/k; q carries DK^-1/2)
    convqk_kernel<<<dim3(BT, NH), 256>>>(qp, conv_q, qc, 0.0625f);
    convqk_kernel<<<dim3(BT, NH), 256>>>(kp, conv_k, kc, 1.0f);
    convv_kernel<<<dim3(BT, VD / 256), 256>>>(vp, conv_v);

    // sequential gated delta-rule recurrence (96 persistent CTAs)
    recur_kernel<<<96, 256>>>();

    // gated RMSNorm, then output projection
    normgate_kernel<<<dim3(BT, NH), 256>>>(onw);
    gemm128<<<dim3(HID / 128, BT / 128), 256>>>(ong, Wo, (float*)d_out, BT, HID, VD);
}

// round 4
// speedup vs baseline: 2.8587x; 2.8587x over previous
#include <cuda_runtime.h>
#include <cuda_bf16.h>
#include <cstdint>

// ---------------- problem dims ----------------
#define B_   2
#define T_   2048
#define HID  2048
#define NH   6
#define DK   256
#define DV   512
#define KD   1536      // NH*DK
#define VD   3072      // NH*DV
#define BT   4096      // B_*T_
#define CK   4

typedef unsigned long long ull;

// ---------------- scratch (device globals; no allocs allowed) ----------------
__device__ float d_QP[BT * KD];
__device__ float d_KP[BT * KD];
__device__ float d_VP[(size_t)BT * VD];
__device__ float d_GP[(size_t)BT * VD];
__device__ float d_Qc[BT * KD];
__device__ float d_Kc[BT * KD];
__device__ float d_Vc[(size_t)BT * VD];
__device__ float d_EG[BT * NH];
__device__ float d_Beta[BT * NH];
__device__ float d_O[(size_t)BT * VD];
__device__ float d_ONG[(size_t)BT * VD];

// bf16 split operand buffers
__device__ __nv_bfloat16 d_Hh[(size_t)BT * HID];
__device__ __nv_bfloat16 d_Hl[(size_t)BT * HID];
__device__ __nv_bfloat16 d_Wqh[(size_t)HID * KD];
__device__ __nv_bfloat16 d_Wql[(size_t)HID * KD];
__device__ __nv_bfloat16 d_Wkh[(size_t)HID * KD];
__device__ __nv_bfloat16 d_Wkl[(size_t)HID * KD];
__device__ __nv_bfloat16 d_Wvh[(size_t)HID * VD];
__device__ __nv_bfloat16 d_Wvl[(size_t)HID * VD];
__device__ __nv_bfloat16 d_Wgh[(size_t)HID * VD];
__device__ __nv_bfloat16 d_Wgl[(size_t)HID * VD];
__device__ __nv_bfloat16 d_Woh[(size_t)VD * HID];
__device__ __nv_bfloat16 d_Wol[(size_t)VD * HID];
__device__ __nv_bfloat16 d_Gh[(size_t)BT * VD];
__device__ __nv_bfloat16 d_Gl[(size_t)BT * VD];

// ---------------- packed f32x2 helpers (recurrence) ----------------
__device__ __forceinline__ ull fma2(ull a, ull b, ull c) {
    ull d;
    asm("fma.rn.f32x2 %0, %1, %2, %3;" : "=l"(d) : "l"(a), "l"(b), "l"(c));
    return d;
}
__device__ __forceinline__ ull mul2(ull a, ull b) {
    ull d;
    asm("mul.rn.f32x2 %0, %1, %2;" : "=l"(d) : "l"(a), "l"(b));
    return d;
}
__device__ __forceinline__ ull pack2(float lo, float hi) {
    ull d;
    asm("mov.b64 %0, {%1, %2};" : "=l"(d) : "f"(lo), "f"(hi));
    return d;
}
__device__ __forceinline__ void unpack2(ull v, float& lo, float& hi) {
    asm("mov.b64 {%0, %1}, %2;" : "=f"(lo), "=f"(hi) : "l"(v));
}
__device__ __forceinline__ float sigm(float x) { return 1.0f / (1.0f + __expf(-x)); }
__device__ __forceinline__ float wredux(float v) {
#pragma unroll
    for (int m = 16; m > 0; m >>= 1) v += __shfl_xor_sync(0xffffffffu, v, m);
    return v;
}

// ---------------- mma.sync bf16 GEMM machinery (family-common PTX) ----------------
__device__ __forceinline__ uint32_t smem_u32(const void* p) {
    uint32_t a;
    asm("{ .reg .u64 t; cvta.to.shared.u64 t, %1; cvt.u32.u64 %0, t; }" : "=r"(a) : "l"(p));
    return a;
}
// pack two floats to bf16x2: low half = x, high half = y
__device__ __forceinline__ uint32_t pkbf(float x, float y) {
    uint32_t r;
    asm("cvt.rn.bf16x2.f32 %0, %1, %2;" : "=r"(r) : "f"(y), "f"(x));
    return r;
}
__device__ __forceinline__ void ldsm_x4(uint32_t* r, uint32_t a) {
    asm volatile("ldmatrix.sync.aligned.m8n8.x4.shared.b16 {%0,%1,%2,%3}, [%4];"
                 : "=r"(r[0]), "=r"(r[1]), "=r"(r[2]), "=r"(r[3]) : "r"(a));
}
__device__ __forceinline__ void ldsm_x4_t(uint32_t* r, uint32_t a) {
    asm volatile("ldmatrix.sync.aligned.m8n8.x4.trans.shared.b16 {%0,%1,%2,%3}, [%4];"
                 : "=r"(r[0]), "=r"(r[1]), "=r"(r[2]), "=r"(r[3]) : "r"(a));
}
__device__ __forceinline__ void mma_bf16(float* d, const uint32_t* a, const uint32_t* b) {
    asm volatile(
        "mma.sync.aligned.m16n8k16.row.col.f32.bf16.bf16.f32 "
        "{%0,%1,%2,%3}, {%4,%5,%6,%7}, {%8,%9}, {%0,%1,%2,%3};"
        : "+f"(d[0]), "+f"(d[1]), "+f"(d[2]), "+f"(d[3])
        : "r"(a[0]), "r"(a[1]), "r"(a[2]), "r"(a[3]), "r"(b[0]), "r"(b[1]));
}
__device__ __forceinline__ void cpa16(uint32_t dst, const void* src) {
    asm volatile("cp.async.cg.shared.global [%0], [%1], 16;" :: "r"(dst), "l"(src));
}
#define CP_COMMIT() asm volatile("cp.async.commit_group;" ::: "memory")
#define CP_WAIT1()  asm volatile("cp.async.wait_group 1;" ::: "memory")

// tiles
#define BM 128
#define BN 128
#define BKf 32
#define STAGES 3
#define A_STR 80     // bytes per A-tile row (32 bf16 = 64B + 16 pad) -> 5r mod 8 permutation
#define B_STR 272    // bytes per B-tile row (128 bf16 = 256B + 16 pad) -> 17r mod 8 permutation
#define AT_BYTES (128 * A_STR)                 // 10240
#define BTI_BYTES (32 * B_STR)                 // 8704
#define OFF_AH 0
#define OFF_AL AT_BYTES
#define OFF_BH (2 * AT_BYTES)
#define OFF_BL (2 * AT_BYTES + BTI_BYTES)
#define STAGE_BYTES (2 * AT_BYTES + 2 * BTI_BYTES)   // 37888
#define SMEM_GB (STAGES * STAGE_BYTES)               // 113664

__device__ __forceinline__ void g_issue(uint32_t st,
                                        const __nv_bfloat16* __restrict__ Ah,
                                        const __nv_bfloat16* __restrict__ Al,
                                        const __nv_bfloat16* __restrict__ Bh,
                                        const __nv_bfloat16* __restrict__ Bl,
                                        int m0, int n0, int kt, int K, int N, int tid) {
#pragma unroll
    for (int half = 0; half < 2; half++) {
        int r = (tid >> 2) + half * 64;
        int ke = (tid & 3) * 8;
        const size_t ga = (size_t)(m0 + r) * K + kt * BKf + ke;
        uint32_t so = st + r * A_STR + ke * 2;
        cpa16(so + OFF_AH, Ah + ga);
        cpa16(so + OFF_AL, Al + ga);
    }
#pragma unroll
    for (int half = 0; half < 2; half++) {
        int r = (tid >> 4) + half * 16;
        int ke = (tid & 15) * 8;
        const size_t gb = (size_t)(kt * BKf + r) * N + n0 + ke;
        uint32_t so = st + r * B_STR + ke * 2;
        cpa16(so + OFF_BH, Bh + gb);
        cpa16(so + OFF_BL, Bl + gb);
    }
}

__device__ __forceinline__ void g_compute(uint32_t st, int wid, int lane, float (*acc)[8][4]) {
    const int wm = (wid & 3) * 32, wn = (wid >> 2) * 64;
    const int arow = lane & 15;
    const int acg = (lane >> 4) * 8;
    const int brow = (lane & 7) + ((lane >> 3) & 1) * 8;
    const int bcg = (lane >> 4) * 8;
#pragma unroll
    for (int ks = 0; ks < BKf; ks += 16) {
        uint32_t ah[2][4], al[2][4], bh[4][4], bl[4][4];
#pragma unroll
        for (int mt = 0; mt < 2; mt++) {
            uint32_t ad = st + OFF_AH + (wm + mt * 16 + arow) * A_STR + (ks + acg) * 2;
            ldsm_x4(ah[mt], ad);
            ldsm_x4(al[mt], ad + AT_BYTES);
        }
#pragma unroll
        for (int nt = 0; nt < 4; nt++) {
            uint32_t bd = st + OFF_BH + (ks + brow) * B_STR + (wn + nt * 16 + bcg) * 2;
            ldsm_x4_t(bh[nt], bd);
            ldsm_x4_t(bl[nt], bd + BTI_BYTES);
        }
#pragma unroll
        for (int mt = 0; mt < 2; mt++)
#pragma unroll
            for (int j = 0; j < 8; j++)
                mma_bf16(acc[mt][j], ah[mt], &bh[j >> 1][(j & 1) * 2]);
#pragma unroll
        for (int mt = 0; mt < 2; mt++)
#pragma unroll
            for (int j = 0; j < 8; j++)
                mma_bf16(acc[mt][j], ah[mt], &bl[j >> 1][(j & 1) * 2]);
#pragma unroll
        for (int mt = 0; mt < 2; mt++)
#pragma unroll
            for (int j = 0; j < 8; j++)
                mma_bf16(acc[mt][j], al[mt], &bh[j >> 1][(j & 1) * 2]);
    }
}

// C[M,N] = A[M,K] @ B[K,N]; operands pre-split hi/lo bf16, fp32 out
__global__ __launch_bounds__(256, 1) void gemm_bf(const __nv_bfloat16* __restrict__ Ah,
                                                  const __nv_bfloat16* __restrict__ Al,
                                                  const __nv_bfloat16* __restrict__ Bh,
                                                  const __nv_bfloat16* __restrict__ Bl,
                                                  float* __restrict__ C,
                                                  int M, int N, int K) {
    extern __shared__ char smem[];
    const uint32_t sb = smem_u32(smem);
    const int tid = threadIdx.x, lane = tid & 31, wid = tid >> 5;
    const int m0 = blockIdx.y * BM, n0 = blockIdx.x * BN;
    const int NT = K / BKf;

    float acc[2][8][4];
#pragma unroll
    for (int mt = 0; mt < 2; mt++)
#pragma unroll
        for (int j = 0; j < 8; j++)
#pragma unroll
            for (int p = 0; p < 4; p++) acc[mt][j][p] = 0.0f;

    g_issue(sb, Ah, Al, Bh, Bl, m0, n0, 0, K, N, tid);
    CP_COMMIT();
    g_issue(sb + STAGE_BYTES, Ah, Al, Bh, Bl, m0, n0, 1, K, N, tid);
    CP_COMMIT();

    for (int kt = 0; kt < NT; kt++) {
        CP_WAIT1();
        __syncthreads();
        const int pf = kt + 2;
        if (pf < NT)
            g_issue(sb + (pf % STAGES) * STAGE_BYTES, Ah, Al, Bh, Bl, m0, n0, pf, K, N, tid);
        CP_COMMIT();
        g_compute(sb + (kt % STAGES) * STAGE_BYTES, wid, lane, acc);
    }

    const int wm = (wid & 3) * 32, wn = (wid >> 2) * 64;
    const int g = lane >> 2, t = lane & 3;
#pragma unroll
    for (int mt = 0; mt < 2; mt++)
#pragma unroll
        for (int j = 0; j < 8; j++) {
            float* p = C + (size_t)(m0 + wm + mt * 16 + g) * N + n0 + wn + j * 8 + t * 2;
            float2 c0 = make_float2(acc[mt][j][0], acc[mt][j][1]);
            float2 c1 = make_float2(acc[mt][j][2], acc[mt][j][3]);
            *(float2*)p = c0;
            *(float2*)(p + (size_t)8 * N) = c1;
        }
}

// ---------------- hi/lo bf16 split (elementwise) ----------------
__global__ __launch_bounds__(256) void split_kernel(const float4* __restrict__ src,
                                                    uint2* __restrict__ h,
                                                    uint2* __restrict__ l, int n4) {
    int i = blockIdx.x * 256 + threadIdx.x;
    if (i >= n4) return;
    float4 v = src[i];
    uint32_t h01 = pkbf(v.x, v.y), h23 = pkbf(v.z, v.w);
    float hx = __uint_as_float(h01 << 16);
    float hy = __uint_as_float(h01 & 0xffff0000u);
    float hz = __uint_as_float(h23 << 16);
    float hw = __uint_as_float(h23 & 0xffff0000u);
    uint2 H = make_uint2(h01, h23);
    uint2 L = make_uint2(pkbf(v.x - hx, v.y - hy), pkbf(v.z - hz, v.w - hw));
    h[i] = H;
    l[i] = L;
}

// ---------------- gate projections: g -> exp(g), beta ----------------
__global__ __launch_bounds__(256) void gate_kernel(const float* __restrict__ H,
                                                   const float* __restrict__ Wa,
                                                   const float* __restrict__ Wb,
                                                   const float* __restrict__ A_log,
                                                   const float* __restrict__ dt_bias) {
    __shared__ float hrow[HID];
    const int bt = blockIdx.x;
    const int tid = threadIdx.x;
    for (int i = tid; i < HID; i += 256) hrow[i] = H[(size_t)bt * HID + i];
    __syncthreads();
    const int w = tid >> 5, lane = tid & 31;
    for (int d = w; d < 12; d += 8) {
        const int head = d % 6;
        const float* Wc = (d < 6) ? Wa : Wb;
        float s = 0.0f;
        for (int i = lane; i < HID; i += 32) s += hrow[i] * Wc[i * NH + head];
#pragma unroll
        for (int m = 16; m > 0; m >>= 1) s += __shfl_xor_sync(0xffffffffu, s, m);
        if (lane == 0) {
            if (d < 6) {
                float x = s + dt_bias[head];
                float sp = (x > 20.0f) ? x : log1pf(expf(x));
                float g = -expf(A_log[head]) * sp;
                d_EG[bt * NH + head] = expf(g);
            } else {
                d_Beta[bt * NH + head] = sigm(s);
            }
        }
    }
}

// ---------------- causal depthwise conv + silu + per-head l2norm (q/k) ----------------
__global__ __launch_bounds__(256) void convqk_kernel(const float* __restrict__ P,
                                                     const float* __restrict__ W,
                                                     float* __restrict__ out,
                                                     float scale) {
    const int bt = blockIdx.x;
    const int h = blockIdx.y;
    const int c = threadIdx.x;
    const int ch = h * DK + c;
    const int t = bt & (T_ - 1);
    float acc = 0.0f;
#pragma unroll
    for (int j = 0; j < CK; j++) {
        int tt = t - (CK - 1) + j;
        if (tt >= 0) acc += P[(size_t)(bt - (CK - 1) + j) * KD + ch] * W[ch * CK + j];
    }
    float y = acc * sigm(acc);  // silu

    __shared__ float red[8];
    float ss = y * y;
#pragma unroll
    for (int m = 16; m > 0; m >>= 1) ss += __shfl_xor_sync(0xffffffffu, ss, m);
    if ((c & 31) == 0) red[c >> 5] = ss;
    __syncthreads();
    float tot = 0.0f;
#pragma unroll
    for (int i = 0; i < 8; i++) tot += red[i];
    float r = rsqrtf(tot + 1e-6f);
    out[(size_t)bt * KD + ch] = y * r * scale;
}

// ---------------- causal depthwise conv + silu (v) ----------------
__global__ __launch_bounds__(256) void convv_kernel(const float* __restrict__ P,
                                                    const float* __restrict__ W) {
    const int bt = blockIdx.x;
    const int ch = blockIdx.y * 256 + threadIdx.x;
    const int t = bt & (T_ - 1);
    float acc = 0.0f;
#pragma unroll
    for (int j = 0; j < CK; j++) {
        int tt = t - (CK - 1) + j;
        if (tt >= 0) acc += P[(size_t)(bt - (CK - 1) + j) * VD + ch] * W[ch * CK + j];
    }
    d_Vc[(size_t)bt * VD + ch] = acc * sigm(acc);
}

// ---------------- gated delta-rule recurrence ----------------
__device__ __forceinline__ void recur_load(const float* Kb, const float* Qb, const float* Vb,
                                           int bt, int h, float kk[8], float qq[8], float vv[8],
                                           float& eg, float& bet) {
    float4 k0 = *(const float4*)(Kb + (size_t)bt * KD);
    float4 k1 = *(const float4*)(Kb + (size_t)bt * KD + 4);
    float4 q0 = *(const float4*)(Qb + (size_t)bt * KD);
    float4 q1 = *(const float4*)(Qb + (size_t)bt * KD + 4);
    float4 v0 = *(const float4*)(Vb + (size_t)bt * VD);
    float4 v1 = *(const float4*)(Vb + (size_t)bt * VD + 4);
    kk[0] = k0.x; kk[1] = k0.y; kk[2] = k0.z; kk[3] = k0.w;
    kk[4] = k1.x; kk[5] = k1.y; kk[6] = k1.z; kk[7] = k1.w;
    qq[0] = q0.x; qq[1] = q0.y; qq[2] = q0.z; qq[3] = q0.w;
    qq[4] = q1.x; qq[5] = q1.y; qq[6] = q1.z; qq[7] = q1.w;
    vv[0] = v0.x; vv[1] = v0.y; vv[2] = v0.z; vv[3] = v0.w;
    vv[4] = v1.x; vv[5] = v1.y; vv[6] = v1.z; vv[7] = v1.w;
    eg = d_EG[bt * NH + h];
    bet = d_Beta[bt * NH + h];
}

__global__ __launch_bounds__(256, 1) void recur_kernel() {
    const int bid = blockIdx.x;
    const int chunk = bid & 7;
    const int bh = bid >> 3;
    const int b = bh / NH, h = bh % NH;
    const int warp = threadIdx.x >> 5, lane = threadIdx.x & 31;
    const int colbase = chunk * 64 + warp * 8;

    ull S[8][4];
#pragma unroll
    for (int r = 0; r < 8; r++)
#pragma unroll
        for (int p = 0; p < 4; p++) S[r][p] = 0ull;

    const float* Kbase = d_Kc + h * DK + lane * 8;
    const float* Qbase = d_Qc + h * DK + lane * 8;
    const float* Vbase = d_Vc + h * DV + colbase;
    float* Obase = d_O + h * DV + colbase;
    const int bt0 = b * T_;

    float kk[8], qq[8], vv[8], eg, bet;
    recur_load(Kbase, Qbase, Vbase, bt0, h, kk, qq, vv, eg, bet);

    for (int t = 0; t < T_; t++) {
        const int bt = bt0 + t;
        float kn[8], qn[8], vn[8], egn, betn;
        if (t + 1 < T_) recur_load(Kbase, Qbase, Vbase, bt + 1, h, kn, qn, vn, egn, betn);

        // phase 1: kv_pre = k . S (pre-decay)
        ull kv2[4] = {0ull, 0ull, 0ull, 0ull};
#pragma unroll
        for (int r = 0; r < 8; r++) {
            ull k2 = pack2(kk[r], kk[r]);
#pragma unroll
            for (int p = 0; p < 4; p++) kv2[p] = fma2(k2, S[r][p], kv2[p]);
        }
        float kv[8];
        unpack2(kv2[0], kv[0], kv[1]); unpack2(kv2[1], kv[2], kv[3]);
        unpack2(kv2[2], kv[4], kv[5]); unpack2(kv2[3], kv[6], kv[7]);
#pragma unroll
        for (int j = 0; j < 8; j++) kv[j] = wredux(kv[j]);

        // u = (v - eg * kv_pre) * beta
        ull u2[4];
#pragma unroll
        for (int p = 0; p < 4; p++) {
            float u0 = (vv[2 * p]     - eg * kv[2 * p])     * bet;
            float u1 = (vv[2 * p + 1] - eg * kv[2 * p + 1]) * bet;
            u2[p] = pack2(u0, u1);
        }
        const ull eg2 = pack2(eg, eg);

        // phase 2: S = eg*S + k (x) u ; o_partial = q . S
        ull o2[4] = {0ull, 0ull, 0ull, 0ull};
#pragma unroll
        for (int r = 0; r < 8; r++) {
            ull k2 = pack2(kk[r], kk[r]);
            ull q2 = pack2(qq[r], qq[r]);
#pragma unroll
            for (int p = 0; p < 4; p++) {
                S[r][p] = fma2(eg2, S[r][p], mul2(k2, u2[p]));
                o2[p]   = fma2(q2, S[r][p], o2[p]);
            }
        }
        float oo[8];
        unpack2(o2[0], oo[0], oo[1]); unpack2(o2[1], oo[2], oo[3]);
        unpack2(o2[2], oo[4], oo[5]); unpack2(o2[3], oo[6], oo[7]);
#pragma unroll
        for (int j = 0; j < 8; j++) oo[j] = wredux(oo[j]);
        if (lane < 8) Obase[(size_t)bt * VD + lane] = oo[lane];

#pragma unroll
        for (int j = 0; j < 8; j++) { kk[j] = kn[j]; qq[j] = qn[j]; vv[j] = vn[j]; }
        eg = egn; bet = betn;
    }
}

// ---------------- gated RMSNorm ----------------
__global__ __launch_bounds__(256) void normgate_kernel(const float* __restrict__ w) {
    const int bt = blockIdx.x;
    const int h = blockIdx.y;
    const int tid = threadIdx.x;
    const size_t base = (size_t)bt * VD + h * DV;
    float o0 = d_O[base + tid];
    float o1 = d_O[base + tid + 256];
    float ss = o0 * o0 + o1 * o1;
    __shared__ float red[8];
#pragma unroll
    for (int m = 16; m > 0; m >>= 1) ss += __shfl_xor_sync(0xffffffffu, ss, m);
    if ((tid & 31) == 0) red[tid >> 5] = ss;
    __syncthreads();
    float tot = 0.0f;
#pragma unroll
    for (int i = 0; i < 8; i++) tot += red[i];
    float rms = rsqrtf(tot * (1.0f / (float)DV) + 1e-5f);
    float g0 = d_GP[base + tid];
    float g1 = d_GP[base + tid + 256];
    d_ONG[base + tid]       = o0 * rms * w[tid]       * g0 * sigm(g0);
    d_ONG[base + tid + 256] = o1 * rms * w[tid + 256] * g1 * sigm(g1);
}

// ---------------- host launcher ----------------
static inline void do_split(const float* src, __nv_bfloat16* h, __nv_bfloat16* l, size_t n) {
    int n4 = (int)(n / 4);
    split_kernel<<<(n4 + 255) / 256, 256>>>((const float4*)src, (uint2*)h, (uint2*)l, n4);
}

extern "C" void kernel_launch(void* const* d_in, const int* in_sizes, int n_in,
                              void* d_out, int out_size) {
    const float* H       = (const float*)d_in[0];
    const float* Wq      = (const float*)d_in[1];
    const float* Wk      = (const float*)d_in[2];
    const float* Wv      = (const float*)d_in[3];
    const float* Wa      = (const float*)d_in[4];
    const float* Wb      = (const float*)d_in[5];
    const float* Wg      = (const float*)d_in[6];
    const float* Wo      = (const float*)d_in[7];
    const float* conv_q  = (const float*)d_in[8];
    const float* conv_k  = (const float*)d_in[9];
    const float* conv_v  = (const float*)d_in[10];
    const float* A_log   = (const float*)d_in[11];
    const float* dt_bias = (const float*)d_in[12];
    const float* onw     = (const float*)d_in[13];

    float *qp, *kp, *vp, *gp, *qc, *kc, *ong;
    cudaGetSymbolAddress((void**)&qp, d_QP);
    cudaGetSymbolAddress((void**)&kp, d_KP);
    cudaGetSymbolAddress((void**)&vp, d_VP);
    cudaGetSymbolAddress((void**)&gp, d_GP);
    cudaGetSymbolAddress((void**)&qc, d_Qc);
    cudaGetSymbolAddress((void**)&kc, d_Kc);
    cudaGetSymbolAddress((void**)&ong, d_ONG);

    __nv_bfloat16 *hh, *hl, *wqh, *wql, *wkh, *wkl, *wvh, *wvl, *wgh, *wgl, *woh, *wol, *gh, *gl;
    cudaGetSymbolAddress((void**)&hh, d_Hh);   cudaGetSymbolAddress((void**)&hl, d_Hl);
    cudaGetSymbolAddress((void**)&wqh, d_Wqh); cudaGetSymbolAddress((void**)&wql, d_Wql);
    cudaGetSymbolAddress((void**)&wkh, d_Wkh); cudaGetSymbolAddress((void**)&wkl, d_Wkl);
    cudaGetSymbolAddress((void**)&wvh, d_Wvh); cudaGetSymbolAddress((void**)&wvl, d_Wvl);
    cudaGetSymbolAddress((void**)&wgh, d_Wgh); cudaGetSymbolAddress((void**)&wgl, d_Wgl);
    cudaGetSymbolAddress((void**)&woh, d_Woh); cudaGetSymbolAddress((void**)&wol, d_Wol);
    cudaGetSymbolAddress((void**)&gh, d_Gh);   cudaGetSymbolAddress((void**)&gl, d_Gl);

    cudaFuncSetAttribute(gemm_bf, cudaFuncAttributeMaxDynamicSharedMemorySize, SMEM_GB);

    // operand splits
    do_split(H,  hh,  hl,  (size_t)BT * HID);
    do_split(Wq, wqh, wql, (size_t)HID * KD);
    do_split(Wk, wkh, wkl, (size_t)HID * KD);
    do_split(Wv, wvh, wvl, (size_t)HID * VD);
    do_split(Wg, wgh, wgl, (size_t)HID * VD);
    do_split(Wo, woh, wol, (size_t)VD * HID);

    // projections on tensor cores (bf16 split, 3-mma compensated)
    gemm_bf<<<dim3(KD / BN, BT / BM), 256, SMEM_GB>>>(hh, hl, wqh, wql, qp, BT, KD, HID);
    gemm_bf<<<dim3(KD / BN, BT / BM), 256, SMEM_GB>>>(hh, hl, wkh, wkl, kp, BT, KD, HID);
    gemm_bf<<<dim3(VD / BN, BT / BM), 256, SMEM_GB>>>(hh, hl, wvh, wvl, vp, BT, VD, HID);
    gemm_bf<<<dim3(VD / BN, BT / BM), 256, SMEM_GB>>>(hh, hl, wgh, wgl, gp, BT, VD, HID);
    gate_kernel<<<BT, 256>>>(H, Wa, Wb, A_log, dt_bias);

    // conv + act (+ l2norm for q/k; q carries DK^-1/2)
    convqk_kernel<<<dim3(BT, NH), 256>>>(qp, conv_q, qc, 0.0625f);
    convqk_kernel<<<dim3(BT, NH), 256>>>(kp, conv_k, kc, 1.0f);
    convv_kernel<<<dim3(BT, VD / 256), 256>>>(vp, conv_v);

    // sequential gated delta-rule recurrence (96 persistent CTAs)
    recur_kernel<<<96, 256>>>();

    // gated RMSNorm, split, then output projection
    normgate_kernel<<<dim3(BT, NH), 256>>>(onw);
    do_split(ong, gh, gl, (size_t)BT * VD);
    gemm_bf<<<dim3(HID / BN, BT / BM), 256, SMEM_GB>>>(gh, gl, woh, wol, (float*)d_out, BT, HID, VD);
}

// round 5
// speedup vs baseline: 3.2860x; 1.1494x over previous
#include <cuda_runtime.h>
#include <cuda_bf16.h>
#include <cstdint>

// ---------------- problem dims ----------------
#define B_   2
#define T_   2048
#define HID  2048
#define NH   6
#define DK   256
#define DV   512
#define KD   1536      // NH*DK
#define VD   3072      // NH*DV
#define BT   4096      // B_*T_
#define CK   4

typedef unsigned long long ull;

// ---------------- scratch (device globals; no allocs allowed) ----------------
__device__ float d_QP[BT * KD];
__device__ float d_KP[BT * KD];
__device__ float d_VP[(size_t)BT * VD];
__device__ float d_GP[(size_t)BT * VD];
__device__ float d_Qc[BT * KD];
__device__ float d_Kc[BT * KD];
__device__ float d_Vc[(size_t)BT * VD];
__device__ float d_EG[BT * NH];
__device__ float d_Beta[BT * NH];
__device__ float d_O[(size_t)BT * VD];
__device__ float d_ONG[(size_t)BT * VD];

// bf16 split operand buffers
__device__ __nv_bfloat16 d_Hh[(size_t)BT * HID];
__device__ __nv_bfloat16 d_Hl[(size_t)BT * HID];
__device__ __nv_bfloat16 d_Wqh[(size_t)HID * KD];
__device__ __nv_bfloat16 d_Wql[(size_t)HID * KD];
__device__ __nv_bfloat16 d_Wkh[(size_t)HID * KD];
__device__ __nv_bfloat16 d_Wkl[(size_t)HID * KD];
__device__ __nv_bfloat16 d_Wvh[(size_t)HID * VD];
__device__ __nv_bfloat16 d_Wvl[(size_t)HID * VD];
__device__ __nv_bfloat16 d_Wgh[(size_t)HID * VD];
__device__ __nv_bfloat16 d_Wgl[(size_t)HID * VD];
__device__ __nv_bfloat16 d_Woh[(size_t)VD * HID];
__device__ __nv_bfloat16 d_Wol[(size_t)VD * HID];
__device__ __nv_bfloat16 d_Gh[(size_t)BT * VD];
__device__ __nv_bfloat16 d_Gl[(size_t)BT * VD];

// ---------------- packed f32x2 helpers (recurrence) ----------------
__device__ __forceinline__ ull fma2(ull a, ull b, ull c) {
    ull d;
    asm("fma.rn.f32x2 %0, %1, %2, %3;" : "=l"(d) : "l"(a), "l"(b), "l"(c));
    return d;
}
__device__ __forceinline__ ull mul2(ull a, ull b) {
    ull d;
    asm("mul.rn.f32x2 %0, %1, %2;" : "=l"(d) : "l"(a), "l"(b));
    return d;
}
__device__ __forceinline__ ull add2(ull a, ull b) {
    ull d;
    asm("add.rn.f32x2 %0, %1, %2;" : "=l"(d) : "l"(a), "l"(b));
    return d;
}
__device__ __forceinline__ ull pack2(float lo, float hi) {
    ull d;
    asm("mov.b64 %0, {%1, %2};" : "=l"(d) : "f"(lo), "f"(hi));
    return d;
}
__device__ __forceinline__ void unpack2(ull v, float& lo, float& hi) {
    asm("mov.b64 {%0, %1}, %2;" : "=f"(lo), "=f"(hi) : "l"(v));
}
__device__ __forceinline__ float sigm(float x) { return 1.0f / (1.0f + __expf(-x)); }

// ---------------- mma.sync bf16 GEMM machinery (family-common PTX) ----------------
__device__ __forceinline__ uint32_t smem_u32(const void* p) {
    uint32_t a;
    asm("{ .reg .u64 t; cvta.to.shared.u64 t, %1; cvt.u32.u64 %0, t; }" : "=r"(a) : "l"(p));
    return a;
}
// pack two floats to bf16x2: low half = x, high half = y
__device__ __forceinline__ uint32_t pkbf(float x, float y) {
    uint32_t r;
    asm("cvt.rn.bf16x2.f32 %0, %1, %2;" : "=r"(r) : "f"(y), "f"(x));
    return r;
}
__device__ __forceinline__ void ldsm_x4(uint32_t* r, uint32_t a) {
    asm volatile("ldmatrix.sync.aligned.m8n8.x4.shared.b16 {%0,%1,%2,%3}, [%4];"
                 : "=r"(r[0]), "=r"(r[1]), "=r"(r[2]), "=r"(r[3]) : "r"(a));
}
__device__ __forceinline__ void ldsm_x4_t(uint32_t* r, uint32_t a) {
    asm volatile("ldmatrix.sync.aligned.m8n8.x4.trans.shared.b16 {%0,%1,%2,%3}, [%4];"
                 : "=r"(r[0]), "=r"(r[1]), "=r"(r[2]), "=r"(r[3]) : "r"(a));
}
__device__ __forceinline__ void mma_bf16(float* d, const uint32_t* a, const uint32_t* b) {
    asm volatile(
        "mma.sync.aligned.m16n8k16.row.col.f32.bf16.bf16.f32 "
        "{%0,%1,%2,%3}, {%4,%5,%6,%7}, {%8,%9}, {%0,%1,%2,%3};"
        : "+f"(d[0]), "+f"(d[1]), "+f"(d[2]), "+f"(d[3])
        : "r"(a[0]), "r"(a[1]), "r"(a[2]), "r"(a[3]), "r"(b[0]), "r"(b[1]));
}
__device__ __forceinline__ void cpa16(uint32_t dst, const void* src) {
    asm volatile("cp.async.cg.shared.global [%0], [%1], 16;" :: "r"(dst), "l"(src));
}
#define CP_COMMIT() asm volatile("cp.async.commit_group;" ::: "memory")
#define CP_WAIT1()  asm volatile("cp.async.wait_group 1;" ::: "memory")

// tiles
#define BM 128
#define BN 128
#define BKf 32
#define STAGES 3
#define A_STR 80     // bytes per A-tile row (32 bf16 = 64B + 16 pad)
#define B_STR 272    // bytes per B-tile row (128 bf16 = 256B + 16 pad)
#define AT_BYTES (128 * A_STR)                 // 10240
#define BTI_BYTES (32 * B_STR)                 // 8704
#define OFF_AH 0
#define OFF_AL AT_BYTES
#define OFF_BH (2 * AT_BYTES)
#define OFF_BL (2 * AT_BYTES + BTI_BYTES)
#define STAGE_BYTES (2 * AT_BYTES + 2 * BTI_BYTES)   // 37888
#define SMEM_GB (STAGES * STAGE_BYTES)               // 113664

__device__ __forceinline__ void g_issue(uint32_t st,
                                        const __nv_bfloat16* __restrict__ Ah,
                                        const __nv_bfloat16* __restrict__ Al,
                                        const __nv_bfloat16* __restrict__ Bh,
                                        const __nv_bfloat16* __restrict__ Bl,
                                        int m0, int n0, int kt, int K, int N, int tid) {
#pragma unroll
    for (int half = 0; half < 2; half++) {
        int r = (tid >> 2) + half * 64;
        int ke = (tid & 3) * 8;
        const size_t ga = (size_t)(m0 + r) * K + kt * BKf + ke;
        uint32_t so = st + r * A_STR + ke * 2;
        cpa16(so + OFF_AH, Ah + ga);
        cpa16(so + OFF_AL, Al + ga);
    }
#pragma unroll
    for (int half = 0; half < 2; half++) {
        int r = (tid >> 4) + half * 16;
        int ke = (tid & 15) * 8;
        const size_t gb = (size_t)(kt * BKf + r) * N + n0 + ke;
        uint32_t so = st + r * B_STR + ke * 2;
        cpa16(so + OFF_BH, Bh + gb);
        cpa16(so + OFF_BL, Bl + gb);
    }
}

__device__ __forceinline__ void g_compute(uint32_t st, int wid, int lane, float (*acc)[8][4]) {
    const int wm = (wid & 3) * 32, wn = (wid >> 2) * 64;
    const int arow = lane & 15;
    const int acg = (lane >> 4) * 8;
    const int brow = (lane & 7) + ((lane >> 3) & 1) * 8;
    const int bcg = (lane >> 4) * 8;
#pragma unroll
    for (int ks = 0; ks < BKf; ks += 16) {
        uint32_t ah[2][4], al[2][4], bh[4][4], bl[4][4];
#pragma unroll
        for (int mt = 0; mt < 2; mt++) {
            uint32_t ad = st + OFF_AH + (wm + mt * 16 + arow) * A_STR + (ks + acg) * 2;
            ldsm_x4(ah[mt], ad);
            ldsm_x4(al[mt], ad + AT_BYTES);
        }
#pragma unroll
        for (int nt = 0; nt < 4; nt++) {
            uint32_t bd = st + OFF_BH + (ks + brow) * B_STR + (wn + nt * 16 + bcg) * 2;
            ldsm_x4_t(bh[nt], bd);
            ldsm_x4_t(bl[nt], bd + BTI_BYTES);
        }
#pragma unroll
        for (int mt = 0; mt < 2; mt++)
#pragma unroll
            for (int j = 0; j < 8; j++)
                mma_bf16(acc[mt][j], ah[mt], &bh[j >> 1][(j & 1) * 2]);
#pragma unroll
        for (int mt = 0; mt < 2; mt++)
#pragma unroll
            for (int j = 0; j < 8; j++)
                mma_bf16(acc[mt][j], ah[mt], &bl[j >> 1][(j & 1) * 2]);
#pragma unroll
        for (int mt = 0; mt < 2; mt++)
#pragma unroll
            for (int j = 0; j < 8; j++)
                mma_bf16(acc[mt][j], al[mt], &bh[j >> 1][(j & 1) * 2]);
    }
}

// C[M,N] = A[M,K] @ B[K,N]; operands pre-split hi/lo bf16, fp32 out
__global__ __launch_bounds__(256, 1) void gemm_bf(const __nv_bfloat16* __restrict__ Ah,
                                                  const __nv_bfloat16* __restrict__ Al,
                                                  const __nv_bfloat16* __restrict__ Bh,
                                                  const __nv_bfloat16* __restrict__ Bl,
                                                  float* __restrict__ C,
                                                  int M, int N, int K) {
    extern __shared__ char smem[];
    const uint32_t sb = smem_u32(smem);
    const int tid = threadIdx.x, lane = tid & 31, wid = tid >> 5;
    const int m0 = blockIdx.y * BM, n0 = blockIdx.x * BN;
    const int NT = K / BKf;

    float acc[2][8][4];
#pragma unroll
    for (int mt = 0; mt < 2; mt++)
#pragma unroll
        for (int j = 0; j < 8; j++)
#pragma unroll
            for (int p = 0; p < 4; p++) acc[mt][j][p] = 0.0f;

    g_issue(sb, Ah, Al, Bh, Bl, m0, n0, 0, K, N, tid);
    CP_COMMIT();
    g_issue(sb + STAGE_BYTES, Ah, Al, Bh, Bl, m0, n0, 1, K, N, tid);
    CP_COMMIT();

    for (int kt = 0; kt < NT; kt++) {
        CP_WAIT1();
        __syncthreads();
        const int pf = kt + 2;
        if (pf < NT)
            g_issue(sb + (pf % STAGES) * STAGE_BYTES, Ah, Al, Bh, Bl, m0, n0, pf, K, N, tid);
        CP_COMMIT();
        g_compute(sb + (kt % STAGES) * STAGE_BYTES, wid, lane, acc);
    }

    const int wm = (wid & 3) * 32, wn = (wid >> 2) * 64;
    const int g = lane >> 2, t = lane & 3;
#pragma unroll
    for (int mt = 0; mt < 2; mt++)
#pragma unroll
        for (int j = 0; j < 8; j++) {
            float* p = C + (size_t)(m0 + wm + mt * 16 + g) * N + n0 + wn + j * 8 + t * 2;
            float2 c0 = make_float2(acc[mt][j][0], acc[mt][j][1]);
            float2 c1 = make_float2(acc[mt][j][2], acc[mt][j][3]);
            *(float2*)p = c0;
            *(float2*)(p + (size_t)8 * N) = c1;
        }
}

// ---------------- hi/lo bf16 split (elementwise) ----------------
__global__ __launch_bounds__(256) void split_kernel(const float4* __restrict__ src,
                                                    uint2* __restrict__ h,
                                                    uint2* __restrict__ l, int n4) {
    int i = blockIdx.x * 256 + threadIdx.x;
    if (i >= n4) return;
    float4 v = src[i];
    uint32_t h01 = pkbf(v.x, v.y), h23 = pkbf(v.z, v.w);
    float hx = __uint_as_float(h01 << 16);
    float hy = __uint_as_float(h01 & 0xffff0000u);
    float hz = __uint_as_float(h23 << 16);
    float hw = __uint_as_float(h23 & 0xffff0000u);
    uint2 H = make_uint2(h01, h23);
    uint2 L = make_uint2(pkbf(v.x - hx, v.y - hy), pkbf(v.z - hz, v.w - hw));
    h[i] = H;
    l[i] = L;
}

// ---------------- gate projections: g -> exp(g), beta ----------------
__global__ __launch_bounds__(256) void gate_kernel(const float* __restrict__ H,
                                                   const float* __restrict__ Wa,
                                                   const float* __restrict__ Wb,
                                                   const float* __restrict__ A_log,
                                                   const float* __restrict__ dt_bias) {
    __shared__ float hrow[HID];
    const int bt = blockIdx.x;
    const int tid = threadIdx.x;
    for (int i = tid; i < HID; i += 256) hrow[i] = H[(size_t)bt * HID + i];
    __syncthreads();
    const int w = tid >> 5, lane = tid & 31;
    for (int d = w; d < 12; d += 8) {
        const int head = d % 6;
        const float* Wc = (d < 6) ? Wa : Wb;
        float s = 0.0f;
        for (int i = lane; i < HID; i += 32) s += hrow[i] * Wc[i * NH + head];
#pragma unroll
        for (int m = 16; m > 0; m >>= 1) s += __shfl_xor_sync(0xffffffffu, s, m);
        if (lane == 0) {
            if (d < 6) {
                float x = s + dt_bias[head];
                float sp = (x > 20.0f) ? x : log1pf(expf(x));
                float g = -expf(A_log[head]) * sp;
                d_EG[bt * NH + head] = expf(g);
            } else {
                d_Beta[bt * NH + head] = sigm(s);
            }
        }
    }
}

// ---------------- causal depthwise conv + silu + per-head l2norm (q/k) ----------------
__global__ __launch_bounds__(256) void convqk_kernel(const float* __restrict__ P,
                                                     const float* __restrict__ W,
                                                     float* __restrict__ out,
                                                     float scale) {
    const int bt = blockIdx.x;
    const int h = blockIdx.y;
    const int c = threadIdx.x;
    const int ch = h * DK + c;
    const int t = bt & (T_ - 1);
    float acc = 0.0f;
#pragma unroll
    for (int j = 0; j < CK; j++) {
        int tt = t - (CK - 1) + j;
        if (tt >= 0) acc += P[(size_t)(bt - (CK - 1) + j) * KD + ch] * W[ch * CK + j];
    }
    float y = acc * sigm(acc);  // silu

    __shared__ float red[8];
    float ss = y * y;
#pragma unroll
    for (int m = 16; m > 0; m >>= 1) ss += __shfl_xor_sync(0xffffffffu, ss, m);
    if ((c & 31) == 0) red[c >> 5] = ss;
    __syncthreads();
    float tot = 0.0f;
#pragma unroll
    for (int i = 0; i < 8; i++) tot += red[i];
    float r = rsqrtf(tot + 1e-6f);
    out[(size_t)bt * KD + ch] = y * r * scale;
}

// ---------------- causal depthwise conv + silu (v) ----------------
__global__ __launch_bounds__(256) void convv_kernel(const float* __restrict__ P,
                                                    const float* __restrict__ W) {
    const int bt = blockIdx.x;
    const int ch = blockIdx.y * 256 + threadIdx.x;
    const int t = bt & (T_ - 1);
    float acc = 0.0f;
#pragma unroll
    for (int j = 0; j < CK; j++) {
        int tt = t - (CK - 1) + j;
        if (tt >= 0) acc += P[(size_t)(bt - (CK - 1) + j) * VD + ch] * W[ch * CK + j];
    }
    d_Vc[(size_t)bt * VD + ch] = acc * sigm(acc);
}

// ---------------- gated delta-rule recurrence ----------------
// 96 CTAs: (b,h) x 8 chunks of 64 cols. 8 warps per CTA: warp owns 8 cols.
// lane = rg*2+cg: rg 0..15 -> rows rg*16..+15; cg 0..1 -> 4 cols.
// S: 16 rows x 4 cols packed as 16x2 f32x2. Reductions over rows = 4-stage
// butterfly shfl on lane bits 1..4 (masks 2,4,8,16): every lane keeps full sum.
__global__ __launch_bounds__(256, 1) void recur_kernel() {
    const int bid = blockIdx.x;
    const int chunk = bid & 7;
    const int bh = bid >> 3;
    const int b = bh / NH, h = bh % NH;
    const int warp = threadIdx.x >> 5, lane = threadIdx.x & 31;
    const int rg = lane >> 1, cg = lane & 1;

    ull S[16][2];
#pragma unroll
    for (int r = 0; r < 16; r++) { S[r][0] = 0ull; S[r][1] = 0ull; }

    const float* Kb = d_Kc + h * DK + rg * 16;
    const float* Qb = d_Qc + h * DK + rg * 16;
    const float* Vb = d_Vc + h * DV + chunk * 64 + warp * 8 + cg * 4;
    float* Ob = d_O + h * DV + chunk * 64 + warp * 8 + cg * 4;
    const int bt0 = b * T_;

    float kf[16], qf[16];
    float4 vv;
    float eg, bet;
    // load t=0
    {
        const size_t ko = (size_t)bt0 * KD;
#pragma unroll
        for (int j = 0; j < 4; j++) {
            float4 a = *(const float4*)(Kb + ko + j * 4);
            kf[4 * j] = a.x; kf[4 * j + 1] = a.y; kf[4 * j + 2] = a.z; kf[4 * j + 3] = a.w;
            float4 qd = *(const float4*)(Qb + ko + j * 4);
            qf[4 * j] = qd.x; qf[4 * j + 1] = qd.y; qf[4 * j + 2] = qd.z; qf[4 * j + 3] = qd.w;
        }
        vv = *(const float4*)(Vb + (size_t)bt0 * VD);
        eg = d_EG[bt0 * NH + h];
        bet = d_Beta[bt0 * NH + h];
    }

    for (int t = 0; t < T_; t++) {
        const int bt = bt0 + t;
        // prefetch t+1
        float kn[16], qn[16];
        float4 vn = vv;
        float egn = eg, betn = bet;
        if (t + 1 < T_) {
            const size_t ko = (size_t)(bt + 1) * KD;
#pragma unroll
            for (int j = 0; j < 4; j++) {
                float4 a = *(const float4*)(Kb + ko + j * 4);
                kn[4 * j] = a.x; kn[4 * j + 1] = a.y; kn[4 * j + 2] = a.z; kn[4 * j + 3] = a.w;
                float4 qd = *(const float4*)(Qb + ko + j * 4);
                qn[4 * j] = qd.x; qn[4 * j + 1] = qd.y; qn[4 * j + 2] = qd.z; qn[4 * j + 3] = qd.w;
            }
            vn = *(const float4*)(Vb + (size_t)(bt + 1) * VD);
            egn = d_EG[(bt + 1) * NH + h];
            betn = d_Beta[(bt + 1) * NH + h];
        } else {
#pragma unroll
            for (int j = 0; j < 16; j++) { kn[j] = 0.0f; qn[j] = 0.0f; }
        }

        // phase 1: kv = k . S (pre-decay)
        ull kv2a = 0ull, kv2b = 0ull;
#pragma unroll
        for (int r = 0; r < 16; r++) {
            ull k2 = pack2(kf[r], kf[r]);
            kv2a = fma2(k2, S[r][0], kv2a);
            kv2b = fma2(k2, S[r][1], kv2b);
        }
#pragma unroll
        for (int mask = 2; mask <= 16; mask <<= 1) {
            kv2a = add2(kv2a, __shfl_xor_sync(0xffffffffu, kv2a, mask));
            kv2b = add2(kv2b, __shfl_xor_sync(0xffffffffu, kv2b, mask));
        }
        float kv0, kv1, kv2f, kv3;
        unpack2(kv2a, kv0, kv1);
        unpack2(kv2b, kv2f, kv3);

        // u = (v - eg * kv) * beta  (this lane's 4 cols)
        ull u2a = pack2((vv.x - eg * kv0) * bet, (vv.y - eg * kv1) * bet);
        ull u2b = pack2((vv.z - eg * kv2f) * bet, (vv.w - eg * kv3) * bet);
        const ull eg2 = pack2(eg, eg);

        // phase 2: S = eg*S + k (x) u ; o = q . S
        ull o2a = 0ull, o2b = 0ull;
#pragma unroll
        for (int r = 0; r < 16; r++) {
            ull k2 = pack2(kf[r], kf[r]);
            ull q2 = pack2(qf[r], qf[r]);
            S[r][0] = fma2(eg2, S[r][0], mul2(k2, u2a));
            o2a = fma2(q2, S[r][0], o2a);
            S[r][1] = fma2(eg2, S[r][1], mul2(k2, u2b));
            o2b = fma2(q2, S[r][1], o2b);
        }
#pragma unroll
        for (int mask = 2; mask <= 16; mask <<= 1) {
            o2a = add2(o2a, __shfl_xor_sync(0xffffffffu, o2a, mask));
            o2b = add2(o2b, __shfl_xor_sync(0xffffffffu, o2b, mask));
        }
        if (rg == 0) {
            float4 o4;
            unpack2(o2a, o4.x, o4.y);
            unpack2(o2b, o4.z, o4.w);
            *(float4*)(Ob + (size_t)bt * VD) = o4;
        }

#pragma unroll
        for (int j = 0; j < 16; j++) { kf[j] = kn[j]; qf[j] = qn[j]; }
        vv = vn; eg = egn; bet = betn;
    }
}

// ---------------- gated RMSNorm ----------------
__global__ __launch_bounds__(256) void normgate_kernel(const float* __restrict__ w) {
    const int bt = blockIdx.x;
    const int h = blockIdx.y;
    const int tid = threadIdx.x;
    const size_t base = (size_t)bt * VD + h * DV;
    float o0 = d_O[base + tid];
    float o1 = d_O[base + tid + 256];
    float ss = o0 * o0 + o1 * o1;
    __shared__ float red[8];
#pragma unroll
    for (int m = 16; m > 0; m >>= 1) ss += __shfl_xor_sync(0xffffffffu, ss, m);
    if ((tid & 31) == 0) red[tid >> 5] = ss;
    __syncthreads();
    float tot = 0.0f;
#pragma unroll
    for (int i = 0; i < 8; i++) tot += red[i];
    float rms = rsqrtf(tot * (1.0f / (float)DV) + 1e-5f);
    float g0 = d_GP[base + tid];
    float g1 = d_GP[base + tid + 256];
    d_ONG[base + tid]       = o0 * rms * w[tid]       * g0 * sigm(g0);
    d_ONG[base + tid + 256] = o1 * rms * w[tid + 256] * g1 * sigm(g1);
}

// ---------------- streams/events (created once at static init; not device mem) ----------------
struct GdnStreams {
    cudaStream_t s1, s2, s3;
    cudaEvent_t evH, evK, evV, evGB, evG, evWo;
    GdnStreams() {
        cudaStreamCreateWithFlags(&s1, cudaStreamNonBlocking);
        cudaStreamCreateWithFlags(&s2, cudaStreamNonBlocking);
        cudaStreamCreateWithFlags(&s3, cudaStreamNonBlocking);
        cudaEventCreateWithFlags(&evH, cudaEventDisableTiming);
        cudaEventCreateWithFlags(&evK, cudaEventDisableTiming);
        cudaEventCreateWithFlags(&evV, cudaEventDisableTiming);
        cudaEventCreateWithFlags(&evGB, cudaEventDisableTiming);
        cudaEventCreateWithFlags(&evG, cudaEventDisableTiming);
        cudaEventCreateWithFlags(&evWo, cudaEventDisableTiming);
    }
};
static GdnStreams g_s;

static inline void do_split(const float* src, __nv_bfloat16* h, __nv_bfloat16* l,
                            size_t n, cudaStream_t st) {
    int n4 = (int)(n / 4);
    split_kernel<<<(n4 + 255) / 256, 256, 0, st>>>((const float4*)src, (uint2*)h, (uint2*)l, n4);
}

// ---------------- host launcher ----------------
extern "C" void kernel_launch(void* const* d_in, const int* in_sizes, int n_in,
                              void* d_out, int out_size) {
    const float* H       = (const float*)d_in[0];
    const float* Wq      = (const float*)d_in[1];
    const float* Wk      = (const float*)d_in[2];
    const float* Wv      = (const float*)d_in[3];
    const float* Wa      = (const float*)d_in[4];
    const float* Wb      = (const float*)d_in[5];
    const float* Wg      = (const float*)d_in[6];
    const float* Wo      = (const float*)d_in[7];
    const float* conv_q  = (const float*)d_in[8];
    const float* conv_k  = (const float*)d_in[9];
    const float* conv_v  = (const float*)d_in[10];
    const float* A_log   = (const float*)d_in[11];
    const float* dt_bias = (const float*)d_in[12];
    const float* onw     = (const float*)d_in[13];

    float *qp, *kp, *vp, *gp, *qc, *kc, *ong;
    cudaGetSymbolAddress((void**)&qp, d_QP);
    cudaGetSymbolAddress((void**)&kp, d_KP);
    cudaGetSymbolAddress((void**)&vp, d_VP);
    cudaGetSymbolAddress((void**)&gp, d_GP);
    cudaGetSymbolAddress((void**)&qc, d_Qc);
    cudaGetSymbolAddress((void**)&kc, d_Kc);
    cudaGetSymbolAddress((void**)&ong, d_ONG);

    __nv_bfloat16 *hh, *hl, *wqh, *wql, *wkh, *wkl, *wvh, *wvl, *wgh, *wgl, *woh, *wol, *gh, *gl;
    cudaGetSymbolAddress((void**)&hh, d_Hh);   cudaGetSymbolAddress((void**)&hl, d_Hl);
    cudaGetSymbolAddress((void**)&wqh, d_Wqh); cudaGetSymbolAddress((void**)&wql, d_Wql);
    cudaGetSymbolAddress((void**)&wkh, d_Wkh); cudaGetSymbolAddress((void**)&wkl, d_Wkl);
    cudaGetSymbolAddress((void**)&wvh, d_Wvh); cudaGetSymbolAddress((void**)&wvl, d_Wvl);
    cudaGetSymbolAddress((void**)&wgh, d_Wgh); cudaGetSymbolAddress((void**)&wgl, d_Wgl);
    cudaGetSymbolAddress((void**)&woh, d_Woh); cudaGetSymbolAddress((void**)&wol, d_Wol);
    cudaGetSymbolAddress((void**)&gh, d_Gh);   cudaGetSymbolAddress((void**)&gl, d_Gl);

    cudaFuncSetAttribute(gemm_bf, cudaFuncAttributeMaxDynamicSharedMemorySize, SMEM_GB);

    cudaStream_t s0 = 0;  // legacy default stream (capture origin)
    cudaStream_t s1 = g_s.s1, s2 = g_s.s2, s3 = g_s.s3;

    // ---- fork: split H on s0, fan out via evH ----
    do_split(H, hh, hl, (size_t)BT * HID, s0);
    cudaEventRecord(g_s.evH, s0);

    // s0: Q chain
    do_split(Wq, wqh, wql, (size_t)HID * KD, s0);
    gemm_bf<<<dim3(KD / BN, BT / BM), 256, SMEM_GB, s0>>>(hh, hl, wqh, wql, qp, BT, KD, HID);
    convqk_kernel<<<dim3(BT, NH), 256, 0, s0>>>(qp, conv_q, qc, 0.0625f);

    // s1: K chain
    cudaStreamWaitEvent(s1, g_s.evH, 0);
    do_split(Wk, wkh, wkl, (size_t)HID * KD, s1);
    gemm_bf<<<dim3(KD / BN, BT / BM), 256, SMEM_GB, s1>>>(hh, hl, wkh, wkl, kp, BT, KD, HID);
    convqk_kernel<<<dim3(BT, NH), 256, 0, s1>>>(kp, conv_k, kc, 1.0f);
    cudaEventRecord(g_s.evK, s1);

    // s2: V chain
    cudaStreamWaitEvent(s2, g_s.evH, 0);
    do_split(Wv, wvh, wvl, (size_t)HID * VD, s2);
    gemm_bf<<<dim3(VD / BN, BT / BM), 256, SMEM_GB, s2>>>(hh, hl, wvh, wvl, vp, BT, VD, HID);
    convv_kernel<<<dim3(BT, VD / 256), 256, 0, s2>>>(vp, conv_v);
    cudaEventRecord(g_s.evV, s2);

    // s3: gate + G chain + Wo split (overlaps recurrence)
    cudaStreamWaitEvent(s3, g_s.evH, 0);
    gate_kernel<<<BT, 256, 0, s3>>>(H, Wa, Wb, A_log, dt_bias);
    cudaEventRecord(g_s.evGB, s3);
    do_split(Wg, wgh, wgl, (size_t)HID * VD, s3);
    gemm_bf<<<dim3(VD / BN, BT / BM), 256, SMEM_GB, s3>>>(hh, hl, wgh, wgl, gp, BT, VD, HID);
    cudaEventRecord(g_s.evG, s3);
    do_split(Wo, woh, wol, (size_t)VD * HID, s3);
    cudaEventRecord(g_s.evWo, s3);

    // ---- join for recurrence on s0 ----
    cudaStreamWaitEvent(s0, g_s.evK, 0);
    cudaStreamWaitEvent(s0, g_s.evV, 0);
    cudaStreamWaitEvent(s0, g_s.evGB, 0);
    recur_kernel<<<96, 256, 0, s0>>>();

    // ---- epilogue on s0 ----
    cudaStreamWaitEvent(s0, g_s.evG, 0);
    normgate_kernel<<<dim3(BT, NH), 256, 0, s0>>>(onw);
    do_split(ong, gh, gl, (size_t)BT * VD, s0);
    cudaStreamWaitEvent(s0, g_s.evWo, 0);
    gemm_bf<<<dim3(HID / BN, BT / BM), 256, SMEM_GB, s0>>>(gh, gl, woh, wol, (float*)d_out, BT, HID, VD);
}